// round 8
// baseline (speedup 1.0000x reference)
#include <cuda_runtime.h>
#include <cstdint>

#define RPB 128
#define THREADS 256

static __device__ __forceinline__ uint32_t cvt_tf32(float f) {
    uint32_t r;
    asm("cvt.rn.tf32.f32 %0, %1;" : "=r"(r) : "f"(f));
    return r;
}

static __device__ __forceinline__ void mma_tf32(float* d,
    uint32_t a0, uint32_t a1, uint32_t a2, uint32_t a3,
    uint32_t b0, uint32_t b1)
{
    asm volatile("mma.sync.aligned.m16n8k8.row.col.f32.tf32.tf32.f32 "
        "{%0,%1,%2,%3}, {%4,%5,%6,%7}, {%8,%9}, {%0,%1,%2,%3};"
        : "+f"(d[0]), "+f"(d[1]), "+f"(d[2]), "+f"(d[3])
        : "r"(a0), "r"(a1), "r"(a2), "r"(a3), "r"(b0), "r"(b1));
}

// Stage 1: quad transpose (xor 1). Lane's chunk m = cols 16m + 4*(tigh+2*odd).
static __device__ __forceinline__ void quad_transpose(
    const float (&v)[8][2], float4 (&c)[4], int odd)
{
    #pragma unroll
    for (int m = 0; m < 4; m++) {
        const int j0 = 2 * m, j1 = 2 * m + 1;
        float send0 = odd ? v[j0][0] : v[j1][0];
        float send1 = odd ? v[j0][1] : v[j1][1];
        float own0  = odd ? v[j1][0] : v[j0][0];
        float own1  = odd ? v[j1][1] : v[j0][1];
        float r0 = __shfl_xor_sync(~0u, send0, 1);
        float r1 = __shfl_xor_sync(~0u, send1, 1);
        c[m].x = odd ? r0 : own0;
        c[m].y = odd ? r1 : own1;
        c[m].z = odd ? own0 : r0;
        c[m].w = odd ? own1 : r1;
    }
}

// Stage 2: quad-pair exchange (xor 4) of chunks {1,3}; each 8-lane group then
// writes one full 128B line of one row per STG.128 -> full store wavefronts.
static __device__ __forceinline__ void pair_store(
    float4 (&c)[4], float* op, long offE, long offO,
    int colsub, int peven, bool okE, bool okO)
{
    float4 x1, x3;
    x1.x = __shfl_xor_sync(~0u, c[1].x, 4);
    x1.y = __shfl_xor_sync(~0u, c[1].y, 4);
    x1.z = __shfl_xor_sync(~0u, c[1].z, 4);
    x1.w = __shfl_xor_sync(~0u, c[1].w, 4);
    x3.x = __shfl_xor_sync(~0u, c[3].x, 4);
    x3.y = __shfl_xor_sync(~0u, c[3].y, 4);
    x3.z = __shfl_xor_sync(~0u, c[3].z, 4);
    x3.w = __shfl_xor_sync(~0u, c[3].w, 4);
    if (okE) *(float4*)(op + offE + (peven ? 0 : 16) + colsub)      = peven ? c[0] : x1;
    if (okO) *(float4*)(op + offO + (peven ? 16 : 0) + colsub)      = peven ? x1 : c[0];
    if (okE) *(float4*)(op + offE + 32 + (peven ? 0 : 16) + colsub) = peven ? c[2] : x3;
    if (okO) *(float4*)(op + offO + 32 + (peven ? 16 : 0) + colsub) = peven ? x3 : c[2];
}

// 256 threads, 8 warps; warp w owns rows w*16..w*16+15 x all 64 protos.
// B is staged fragment-major: 16B unit V = ks*128 + (g*8+tau)*2 + w holds
// B[n][k] for n=(u*4+j')*8+g (u = w ^ (g&1)), k = ks*8+tau -> each lane's
// 8 j-values per (ks,tau) are two conflict-free LDS.128.
__global__ __launch_bounds__(THREADS, 3) void assign_mma_kernel(
    const float4* __restrict__ feat4,
    const float* __restrict__ proto,
    float* __restrict__ out, int nrows)
{
    __shared__ uint4 A_s[RPB * 16];   // 32 KB
    __shared__ uint4 B_s[64 * 16];    // 16 KB, fragment-major

    const int tid = threadIdx.x;
    const long base = (long)blockIdx.x * RPB;
    const int rows = min(RPB, nrows - (int)base);
    const int cnt4 = rows * 16;

    // ---- stage features (tf32, swizzled); zero-fill OOB rows ----
    const float4* g4 = feat4 + base * 16;
    #pragma unroll
    for (int i = 0; i < 8; i++) {
        int idx = tid + i * THREADS;
        float4 v = make_float4(0.f, 0.f, 0.f, 0.f);
        if (idx < cnt4) v = g4[idx];
        uint4 t;
        t.x = cvt_tf32(v.x); t.y = cvt_tf32(v.y);
        t.z = cvt_tf32(v.z); t.w = cvt_tf32(v.w);
        int r = idx >> 4, c = idx & 15;
        A_s[(r << 4) | (c ^ (r & 7))] = t;
    }
    // ---- stage prototypes fragment-major ----
    #pragma unroll
    for (int l = 0; l < 4; l++) {
        int V = tid + l * THREADS;          // unit 0..1023
        int ks = V >> 7, rem = V & 127;
        int w2 = rem & 1, gt = rem >> 1;
        int g = gt >> 3, tau = gt & 7;
        int u = w2 ^ (g & 1);
        int k = ks * 8 + tau;
        uint4 t;
        t.x = cvt_tf32(proto[((u * 4 + 0) * 8 + g) * 64 + k]);
        t.y = cvt_tf32(proto[((u * 4 + 1) * 8 + g) * 64 + k]);
        t.z = cvt_tf32(proto[((u * 4 + 2) * 8 + g) * 64 + k]);
        t.w = cvt_tf32(proto[((u * 4 + 3) * 8 + g) * 64 + k]);
        B_s[V] = t;
    }
    __syncthreads();

    const int w = tid >> 5, lane = tid & 31;
    const int gid = lane >> 2, tig = lane & 3;
    const int odd = tig & 1, tigh = tig >> 1;
    const int gpar = gid & 1;
    const int colsub = 4 * (tigh + 2 * odd);
    const int peven = ((gid & 1) == 0);
    const int sw = gid << 2;
    const int rb = w * 16;

    const uint32_t* As32 = (const uint32_t*)A_s;
    const uint4* Bf4 = (const uint4*)B_s;
    const int ub = (gid * 8 + tig) * 2;     // unit base for tau=tig

    // ---- GEMM + fused row-norm accumulation ----
    float acc[8][4];
    float nrm[2] = {0.f, 0.f};
    #pragma unroll
    for (int j = 0; j < 8; j++)
        #pragma unroll
        for (int e = 0; e < 4; e++) acc[j][e] = 0.f;

    #pragma unroll
    for (int ks = 0; ks < 8; ks++) {
        int o0 = (ks * 8 + tig) ^ sw;
        int o1 = (ks * 8 + tig + 4) ^ sw;
        int r = rb + gid;
        uint32_t a0 = As32[r * 64 + o0];
        uint32_t a1 = As32[(r + 8) * 64 + o0];
        uint32_t a2 = As32[r * 64 + o1];
        uint32_t a3 = As32[(r + 8) * 64 + o1];
        float f0 = __uint_as_float(a0), f1 = __uint_as_float(a1);
        float f2 = __uint_as_float(a2), f3 = __uint_as_float(a3);
        nrm[0] += f0 * f0 + f2 * f2;   // row r
        nrm[1] += f1 * f1 + f3 * f3;   // row r+8

        uint4 b0lo = Bf4[ks * 128 + ub + gpar];            // k=ks*8+tig,  j=0..3
        uint4 b0hi = Bf4[ks * 128 + ub + (1 - gpar)];      // j=4..7
        uint4 b1lo = Bf4[ks * 128 + ub + 8 + gpar];        // k=+4, j=0..3
        uint4 b1hi = Bf4[ks * 128 + ub + 8 + (1 - gpar)];  // j=4..7

        mma_tf32(acc[0], a0, a1, a2, a3, b0lo.x, b1lo.x);
        mma_tf32(acc[1], a0, a1, a2, a3, b0lo.y, b1lo.y);
        mma_tf32(acc[2], a0, a1, a2, a3, b0lo.z, b1lo.z);
        mma_tf32(acc[3], a0, a1, a2, a3, b0lo.w, b1lo.w);
        mma_tf32(acc[4], a0, a1, a2, a3, b0hi.x, b1hi.x);
        mma_tf32(acc[5], a0, a1, a2, a3, b0hi.y, b1hi.y);
        mma_tf32(acc[6], a0, a1, a2, a3, b0hi.z, b1hi.z);
        mma_tf32(acc[7], a0, a1, a2, a3, b0hi.w, b1hi.w);
    }

    // ---- scales: quad-reduce; sc = 5 / max(||f||, eps)  (tau=0.2) ----
    float sc[2];
    #pragma unroll
    for (int hf = 0; hf < 2; hf++) {
        float s = nrm[hf];
        s += __shfl_xor_sync(~0u, s, 1);
        s += __shfl_xor_sync(~0u, s, 2);
        sc[hf] = 5.0f / fmaxf(sqrtf(s), 1e-8f);
    }

    // ---- epilogue: scale, exp, quad-reduce sum, full-line stores ----
    #pragma unroll
    for (int hf = 0; hf < 2; hf++) {
        int rE = rb + hf * 8 + (gid & ~1);
        int rO = rE + 1;
        float scv = sc[hf];
        bool okE = (rE < rows), okO = (rO < rows);
        long offE = (base + rE) * 64;
        long offO = (base + rO) * 64;

        float lg[8][2], ex[8][2];
        float s = 0.f;
        #pragma unroll
        for (int j = 0; j < 8; j++) {
            lg[j][0] = acc[j][2 * hf]     * scv;
            lg[j][1] = acc[j][2 * hf + 1] * scv;
            ex[j][0] = __expf(lg[j][0]);       // |logit| <= 5
            ex[j][1] = __expf(lg[j][1]);
            s += ex[j][0] + ex[j][1];
        }
        s += __shfl_xor_sync(~0u, s, 1);
        s += __shfl_xor_sync(~0u, s, 2);
        float inv = 1.0f / s;
        #pragma unroll
        for (int j = 0; j < 8; j++) {
            ex[j][0] *= inv;
            ex[j][1] *= inv;
        }

        float4 c[4];
        quad_transpose(lg, c, odd);
        pair_store(c, out, offE, offO, colsub, peven, okE, okO);
        quad_transpose(ex, c, odd);
        pair_store(c, out + (long)nrows * 64, offE, offO, colsub, peven, okE, okO);
    }
}

extern "C" void kernel_launch(void* const* d_in, const int* in_sizes, int n_in,
                              void* d_out, int out_size) {
    const float4* feat4 = (const float4*)d_in[0];
    const float* proto  = (const float*)d_in[1];
    float* out = (float*)d_out;
    int nrows = in_sizes[0] / 64;
    int grid = (nrows + RPB - 1) / RPB;
    assign_mma_kernel<<<grid, THREADS>>>(feat4, proto, out, nrows);
}

// round 9
// speedup vs baseline: 1.0051x; 1.0051x over previous
#include <cuda_runtime.h>
#include <cstdint>

#define RPB 256
#define THREADS 256
#define SMEM_TOTAL (80 * 1024)

static __device__ __forceinline__ uint32_t cvt_tf32(float f) {
    uint32_t r;
    asm("cvt.rn.tf32.f32 %0, %1;" : "=r"(r) : "f"(f));
    return r;
}

static __device__ __forceinline__ void mma_tf32(float* d,
    uint32_t a0, uint32_t a1, uint32_t a2, uint32_t a3,
    uint32_t b0, uint32_t b1)
{
    asm volatile("mma.sync.aligned.m16n8k8.row.col.f32.tf32.tf32.f32 "
        "{%0,%1,%2,%3}, {%4,%5,%6,%7}, {%8,%9}, {%0,%1,%2,%3};"
        : "+f"(d[0]), "+f"(d[1]), "+f"(d[2]), "+f"(d[3])
        : "r"(a0), "r"(a1), "r"(a2), "r"(a3), "r"(b0), "r"(b1));
}

// Stage 1: quad transpose (xor 1). Lane's chunk m = cols 16m + 4*(tigh+2*odd).
static __device__ __forceinline__ void quad_transpose(
    const float (&v)[8][2], float4 (&c)[4], int odd)
{
    #pragma unroll
    for (int m = 0; m < 4; m++) {
        const int j0 = 2 * m, j1 = 2 * m + 1;
        float send0 = odd ? v[j0][0] : v[j1][0];
        float send1 = odd ? v[j0][1] : v[j1][1];
        float own0  = odd ? v[j1][0] : v[j0][0];
        float own1  = odd ? v[j1][1] : v[j0][1];
        float r0 = __shfl_xor_sync(~0u, send0, 1);
        float r1 = __shfl_xor_sync(~0u, send1, 1);
        c[m].x = odd ? r0 : own0;
        c[m].y = odd ? r1 : own1;
        c[m].z = odd ? own0 : r0;
        c[m].w = odd ? own1 : r1;
    }
}

// Stage 2: quad-pair exchange (xor 4) of chunks {1,3}; each 8-lane group then
// writes one full 128B line of one row per STG.128 -> full store wavefronts.
static __device__ __forceinline__ void pair_store(
    float4 (&c)[4], float* op, long offE, long offO,
    int colsub, int peven, bool okE, bool okO)
{
    float4 x1, x3;
    x1.x = __shfl_xor_sync(~0u, c[1].x, 4);
    x1.y = __shfl_xor_sync(~0u, c[1].y, 4);
    x1.z = __shfl_xor_sync(~0u, c[1].z, 4);
    x1.w = __shfl_xor_sync(~0u, c[1].w, 4);
    x3.x = __shfl_xor_sync(~0u, c[3].x, 4);
    x3.y = __shfl_xor_sync(~0u, c[3].y, 4);
    x3.z = __shfl_xor_sync(~0u, c[3].z, 4);
    x3.w = __shfl_xor_sync(~0u, c[3].w, 4);
    if (okE) *(float4*)(op + offE + (peven ? 0 : 16) + colsub)      = peven ? c[0] : x1;
    if (okO) *(float4*)(op + offO + (peven ? 16 : 0) + colsub)      = peven ? x1 : c[0];
    if (okE) *(float4*)(op + offE + 32 + (peven ? 0 : 16) + colsub) = peven ? c[2] : x3;
    if (okO) *(float4*)(op + offO + 32 + (peven ? 16 : 0) + colsub) = peven ? x3 : c[2];
}

// 256 threads, 8 warps; warp w owns 32 rows (w*32..+31) x all 64 protos.
// Each B fragment read is reused across 2 m-chunks -> B crossbar traffic
// per output row halved vs 16-rows/warp.
__global__ __launch_bounds__(THREADS, 2) void assign_mma_kernel(
    const float4* __restrict__ feat4,
    const float4* __restrict__ proto4,
    float* __restrict__ out, int nrows)
{
    extern __shared__ uint4 smem[];
    uint4* A_s = smem;              // 64 KB: 256 rows x 16 uint4
    uint4* B_s = smem + RPB * 16;   // 16 KB: 64 rows x 16 uint4

    const int tid = threadIdx.x;
    const long base = (long)blockIdx.x * RPB;
    const int rows = min(RPB, nrows - (int)base);
    const int cnt4 = rows * 16;

    // ---- stage features (tf32, swizzled); zero-fill OOB rows ----
    const float4* g4 = feat4 + base * 16;
    #pragma unroll
    for (int i = 0; i < 16; i++) {
        int idx = tid + i * THREADS;
        float4 v = make_float4(0.f, 0.f, 0.f, 0.f);
        if (idx < cnt4) v = g4[idx];
        uint4 t;
        t.x = cvt_tf32(v.x); t.y = cvt_tf32(v.y);
        t.z = cvt_tf32(v.z); t.w = cvt_tf32(v.w);
        int r = idx >> 4, c = idx & 15;
        A_s[(r << 4) | (c ^ (r & 7))] = t;
    }
    // ---- stage prototypes (n-major, swizzled) ----
    #pragma unroll
    for (int i = 0; i < 4; i++) {
        int idx = tid + i * THREADS;
        float4 v = proto4[idx];
        uint4 t;
        t.x = cvt_tf32(v.x); t.y = cvt_tf32(v.y);
        t.z = cvt_tf32(v.z); t.w = cvt_tf32(v.w);
        int n = idx >> 4, c = idx & 15;
        B_s[(n << 4) | (c ^ (n & 7))] = t;
    }
    __syncthreads();

    const int w = tid >> 5, lane = tid & 31;
    const int gid = lane >> 2, tig = lane & 3;
    const int odd = tig & 1, tigh = tig >> 1;
    const int colsub = 4 * (tigh + 2 * odd);
    const int peven = ((gid & 1) == 0);
    const int sw = gid << 2;
    const int rb = w * 32;

    const uint32_t* As32 = (const uint32_t*)A_s;
    const uint32_t* Bs32 = (const uint32_t*)B_s;

    // ---- GEMM (2 m-chunks share each B fragment) + fused row norms ----
    float acc[2][8][4];
    float nrm[2][2] = {{0.f, 0.f}, {0.f, 0.f}};
    #pragma unroll
    for (int ch = 0; ch < 2; ch++)
        #pragma unroll
        for (int j = 0; j < 8; j++)
            #pragma unroll
            for (int e = 0; e < 4; e++) acc[ch][j][e] = 0.f;

    #pragma unroll
    for (int ks = 0; ks < 8; ks++) {
        int o0 = (ks * 8 + tig) ^ sw;
        int o1 = (ks * 8 + tig + 4) ^ sw;
        uint32_t b0[8], b1[8];
        #pragma unroll
        for (int j = 0; j < 8; j++) {
            int n = j * 8 + gid;
            b0[j] = Bs32[n * 64 + o0];
            b1[j] = Bs32[n * 64 + o1];
        }
        #pragma unroll
        for (int ch = 0; ch < 2; ch++) {
            int r = rb + ch * 16 + gid;
            uint32_t a0 = As32[r * 64 + o0];
            uint32_t a1 = As32[(r + 8) * 64 + o0];
            uint32_t a2 = As32[r * 64 + o1];
            uint32_t a3 = As32[(r + 8) * 64 + o1];
            float f0 = __uint_as_float(a0), f1 = __uint_as_float(a1);
            float f2 = __uint_as_float(a2), f3 = __uint_as_float(a3);
            nrm[ch][0] += f0 * f0 + f2 * f2;   // row r
            nrm[ch][1] += f1 * f1 + f3 * f3;   // row r+8
            #pragma unroll
            for (int j = 0; j < 8; j++)
                mma_tf32(acc[ch][j], a0, a1, a2, a3, b0[j], b1[j]);
        }
    }

    // ---- scales: quad-reduce; sc = 5 / max(||f||, eps)  (tau=0.2) ----
    float sc[2][2];
    #pragma unroll
    for (int ch = 0; ch < 2; ch++)
        #pragma unroll
        for (int hf = 0; hf < 2; hf++) {
            float s = nrm[ch][hf];
            s += __shfl_xor_sync(~0u, s, 1);
            s += __shfl_xor_sync(~0u, s, 2);
            sc[ch][hf] = 5.0f / fmaxf(sqrtf(s), 1e-8f);
        }

    // ---- epilogue: scale, exp, quad-reduce sum, full-line stores ----
    #pragma unroll
    for (int ch = 0; ch < 2; ch++) {
        #pragma unroll
        for (int hf = 0; hf < 2; hf++) {
            int rE = rb + ch * 16 + hf * 8 + (gid & ~1);
            int rO = rE + 1;
            float scv = sc[ch][hf];
            bool okE = (rE < rows), okO = (rO < rows);
            long offE = (base + rE) * 64;
            long offO = (base + rO) * 64;

            float lg[8][2], ex[8][2];
            float s = 0.f;
            #pragma unroll
            for (int j = 0; j < 8; j++) {
                lg[j][0] = acc[ch][j][2 * hf]     * scv;
                lg[j][1] = acc[ch][j][2 * hf + 1] * scv;
                ex[j][0] = __expf(lg[j][0]);       // |logit| <= 5
                ex[j][1] = __expf(lg[j][1]);
                s += ex[j][0] + ex[j][1];
            }
            s += __shfl_xor_sync(~0u, s, 1);
            s += __shfl_xor_sync(~0u, s, 2);
            float inv = 1.0f / s;
            #pragma unroll
            for (int j = 0; j < 8; j++) {
                ex[j][0] *= inv;
                ex[j][1] *= inv;
            }

            float4 c[4];
            quad_transpose(lg, c, odd);
            pair_store(c, out, offE, offO, colsub, peven, okE, okO);
            quad_transpose(ex, c, odd);
            pair_store(c, out + (long)nrows * 64, offE, offO, colsub, peven, okE, okO);
        }
    }
}

extern "C" void kernel_launch(void* const* d_in, const int* in_sizes, int n_in,
                              void* d_out, int out_size) {
    const float4* feat4  = (const float4*)d_in[0];
    const float4* proto4 = (const float4*)d_in[1];
    float* out = (float*)d_out;
    int nrows = in_sizes[0] / 64;
    cudaFuncSetAttribute(assign_mma_kernel,
                         cudaFuncAttributeMaxDynamicSharedMemorySize, SMEM_TOTAL);
    int grid = (nrows + RPB - 1) / RPB;
    assign_mma_kernel<<<grid, THREADS, SMEM_TOTAL>>>(feat4, proto4, out, nrows);
}

// round 10
// speedup vs baseline: 1.1087x; 1.1031x over previous
#include <cuda_runtime.h>
#include <cstdint>

#define RPB 128
#define THREADS 256
#define SMEM_BYTES (80 * 1024)
// SMEM: A0 [0,32K), A1 [32K,64K), B [64K,80K)

static __device__ __forceinline__ uint32_t smem_u32(const void* p) {
    uint32_t a;
    asm("{ .reg .u64 t; cvta.to.shared.u64 t, %1; cvt.u32.u64 %0, t; }" : "=r"(a) : "l"(p));
    return a;
}
static __device__ __forceinline__ uint32_t cvt_tf32(float f) {
    uint32_t r;
    asm("cvt.rn.tf32.f32 %0, %1;" : "=r"(r) : "f"(f));
    return r;
}
static __device__ __forceinline__ void mma_tf32(float* d,
    uint32_t a0, uint32_t a1, uint32_t a2, uint32_t a3,
    uint32_t b0, uint32_t b1)
{
    asm volatile("mma.sync.aligned.m16n8k8.row.col.f32.tf32.tf32.f32 "
        "{%0,%1,%2,%3}, {%4,%5,%6,%7}, {%8,%9}, {%0,%1,%2,%3};"
        : "+f"(d[0]), "+f"(d[1]), "+f"(d[2]), "+f"(d[3])
        : "r"(a0), "r"(a1), "r"(a2), "r"(a3), "r"(b0), "r"(b1));
}

// Prefetch one 128-row feature tile (raw fp32) into a swizzled SMEM buffer.
static __device__ __forceinline__ void prefetch_tile(
    const float4* gbase, uint32_t abase, int tid, int cnt4)
{
    #pragma unroll
    for (int i = 0; i < 8; i++) {
        int idx = tid + i * THREADS;
        int r = idx >> 4, c = idx & 15;
        uint32_t dst = abase + (((r << 4) | (c ^ (r & 7))) << 4);
        int cidx = (idx < cnt4) ? idx : 0;
        uint32_t sz = (idx < cnt4) ? 16u : 0u;       // OOB -> zero-fill
        asm volatile("cp.async.cg.shared.global [%0], [%1], 16, %2;"
                     :: "r"(dst), "l"(gbase + cidx), "r"(sz) : "memory");
    }
    asm volatile("cp.async.commit_group;" ::: "memory");
}

// Stage 1: quad transpose (xor 1).
static __device__ __forceinline__ void quad_transpose(
    const float (&v)[8][2], float4 (&c)[4], int odd)
{
    #pragma unroll
    for (int m = 0; m < 4; m++) {
        const int j0 = 2 * m, j1 = 2 * m + 1;
        float send0 = odd ? v[j0][0] : v[j1][0];
        float send1 = odd ? v[j0][1] : v[j1][1];
        float own0  = odd ? v[j1][0] : v[j0][0];
        float own1  = odd ? v[j1][1] : v[j0][1];
        float r0 = __shfl_xor_sync(~0u, send0, 1);
        float r1 = __shfl_xor_sync(~0u, send1, 1);
        c[m].x = odd ? r0 : own0;
        c[m].y = odd ? r1 : own1;
        c[m].z = odd ? own0 : r0;
        c[m].w = odd ? own1 : r1;
    }
}

// Stage 2: xor-4 exchange of chunks {1,3}; streaming full-line stores.
static __device__ __forceinline__ void pair_store(
    float4 (&c)[4], float* op, long offE, long offO,
    int colsub, int peven, bool okE, bool okO)
{
    float4 x1, x3;
    x1.x = __shfl_xor_sync(~0u, c[1].x, 4);
    x1.y = __shfl_xor_sync(~0u, c[1].y, 4);
    x1.z = __shfl_xor_sync(~0u, c[1].z, 4);
    x1.w = __shfl_xor_sync(~0u, c[1].w, 4);
    x3.x = __shfl_xor_sync(~0u, c[3].x, 4);
    x3.y = __shfl_xor_sync(~0u, c[3].y, 4);
    x3.z = __shfl_xor_sync(~0u, c[3].z, 4);
    x3.w = __shfl_xor_sync(~0u, c[3].w, 4);
    if (okE) __stcs((float4*)(op + offE + (peven ? 0 : 16) + colsub),      peven ? c[0] : x1);
    if (okO) __stcs((float4*)(op + offO + (peven ? 16 : 0) + colsub),      peven ? x1 : c[0]);
    if (okE) __stcs((float4*)(op + offE + 32 + (peven ? 0 : 16) + colsub), peven ? c[2] : x3);
    if (okO) __stcs((float4*)(op + offO + 32 + (peven ? 16 : 0) + colsub), peven ? x3 : c[2]);
}

// Persistent: 2 CTAs/SM, each loops over tiles with cp.async double buffering.
__global__ __launch_bounds__(THREADS, 2) void assign_mma_kernel(
    const float4* __restrict__ feat4,
    const float4* __restrict__ proto4,
    float* __restrict__ out, int nrows, int ntiles)
{
    extern __shared__ char smem[];
    const uint32_t sbase = smem_u32(smem);
    uint4* B_s = (uint4*)(smem + 65536);

    const int tid = threadIdx.x;
    const int w = tid >> 5, lane = tid & 31;
    const int gid = lane >> 2, tig = lane & 3;
    const int odd = tig & 1, tigh = tig >> 1;
    const int colsub = 4 * (tigh + 2 * odd);
    const int peven = ((gid & 1) == 0);
    const int sw = gid << 2;
    const int rb = w * 16;

    // ---- stage prototypes once (tf32, swizzled) ----
    #pragma unroll
    for (int i = 0; i < 4; i++) {
        int idx = tid + i * THREADS;
        float4 v = proto4[idx];
        uint4 t;
        t.x = cvt_tf32(v.x); t.y = cvt_tf32(v.y);
        t.z = cvt_tf32(v.z); t.w = cvt_tf32(v.w);
        int n = idx >> 4, c = idx & 15;
        B_s[(n << 4) | (c ^ (n & 7))] = t;
    }
    const uint32_t* Bs32 = (const uint32_t*)B_s;

    // ---- prologue: prefetch first tile into buf0 ----
    long tile = blockIdx.x;
    if (tile < ntiles) {
        int rows0 = min(RPB, nrows - (int)(tile * RPB));
        prefetch_tile(feat4 + tile * RPB * 16, sbase, tid, rows0 * 16);
    }

    int it = 0;
    for (; tile < ntiles; tile += gridDim.x, it++) {
        const long base = tile * RPB;
        const int rows = min(RPB, nrows - (int)base);
        const long next = tile + gridDim.x;
        const bool more = next < ntiles;

        // prefetch next tile into alternate buffer
        if (more) {
            int rowsn = min(RPB, nrows - (int)(next * RPB));
            prefetch_tile(feat4 + next * RPB * 16,
                          sbase + (((it + 1) & 1) << 15), tid, rowsn * 16);
        }
        if (more) asm volatile("cp.async.wait_group 1;" ::: "memory");
        else      asm volatile("cp.async.wait_group 0;" ::: "memory");
        __syncthreads();

        const float*    Asf  = (const float*)(smem + ((it & 1) << 15));
        // ---- GEMM + fused row norms (raw fp32 -> cvt at use) ----
        float acc[8][4];
        float nrm[2] = {0.f, 0.f};
        #pragma unroll
        for (int j = 0; j < 8; j++)
            #pragma unroll
            for (int e = 0; e < 4; e++) acc[j][e] = 0.f;

        #pragma unroll
        for (int ks = 0; ks < 8; ks++) {
            int o0 = (ks * 8 + tig) ^ sw;
            int o1 = (ks * 8 + tig + 4) ^ sw;
            int r = rb + gid;
            float f0 = Asf[r * 64 + o0];
            float f1 = Asf[(r + 8) * 64 + o0];
            float f2 = Asf[r * 64 + o1];
            float f3 = Asf[(r + 8) * 64 + o1];
            nrm[0] += f0 * f0 + f2 * f2;   // row r
            nrm[1] += f1 * f1 + f3 * f3;   // row r+8
            uint32_t a0 = cvt_tf32(f0), a1 = cvt_tf32(f1);
            uint32_t a2 = cvt_tf32(f2), a3 = cvt_tf32(f3);
            #pragma unroll
            for (int j = 0; j < 8; j++) {
                int n = j * 8 + gid;
                mma_tf32(acc[j], a0, a1, a2, a3,
                         Bs32[n * 64 + o0], Bs32[n * 64 + o1]);
            }
        }

        // ---- scales: quad-reduce; sc = 5 / max(||f||, eps)  (tau=0.2) ----
        float sc[2];
        #pragma unroll
        for (int hf = 0; hf < 2; hf++) {
            float s = nrm[hf];
            s += __shfl_xor_sync(~0u, s, 1);
            s += __shfl_xor_sync(~0u, s, 2);
            sc[hf] = 5.0f / fmaxf(sqrtf(s), 1e-8f);
        }

        // ---- epilogue ----
        #pragma unroll
        for (int hf = 0; hf < 2; hf++) {
            int rE = rb + hf * 8 + (gid & ~1);
            int rO = rE + 1;
            float scv = sc[hf];
            bool okE = (rE < rows), okO = (rO < rows);
            long offE = (base + rE) * 64;
            long offO = (base + rO) * 64;

            float lg[8][2], ex[8][2];
            float s = 0.f;
            #pragma unroll
            for (int j = 0; j < 8; j++) {
                lg[j][0] = acc[j][2 * hf]     * scv;
                lg[j][1] = acc[j][2 * hf + 1] * scv;
                ex[j][0] = __expf(lg[j][0]);       // |logit| <= 5
                ex[j][1] = __expf(lg[j][1]);
                s += ex[j][0] + ex[j][1];
            }
            s += __shfl_xor_sync(~0u, s, 1);
            s += __shfl_xor_sync(~0u, s, 2);
            float inv = 1.0f / s;
            #pragma unroll
            for (int j = 0; j < 8; j++) {
                ex[j][0] *= inv;
                ex[j][1] *= inv;
            }

            float4 c[4];
            quad_transpose(lg, c, odd);
            pair_store(c, out, offE, offO, colsub, peven, okE, okO);
            quad_transpose(ex, c, odd);
            pair_store(c, out + (long)nrows * 64, offE, offO, colsub, peven, okE, okO);
        }
        __syncthreads();   // all reads of buf (it&1) done before it's overwritten
    }
}

extern "C" void kernel_launch(void* const* d_in, const int* in_sizes, int n_in,
                              void* d_out, int out_size) {
    const float4* feat4  = (const float4*)d_in[0];
    const float4* proto4 = (const float4*)d_in[1];
    float* out = (float*)d_out;
    int nrows = in_sizes[0] / 64;
    int ntiles = (nrows + RPB - 1) / RPB;
    cudaFuncSetAttribute(assign_mma_kernel,
                         cudaFuncAttributeMaxDynamicSharedMemorySize, SMEM_BYTES);
    int grid = 296;                    // 2 persistent CTAs per SM (148 SMs)
    if (grid > ntiles) grid = ntiles;
    assign_mma_kernel<<<grid, THREADS, SMEM_BYTES>>>(feat4, proto4, out, nrows, ntiles);
}

// round 12
// speedup vs baseline: 1.1293x; 1.0186x over previous
#include <cuda_runtime.h>
#include <cstdint>

#define RPB 128
#define THREADS 256
#define SMEM_BYTES (112 * 1024)
// SMEM: A0 [0,32K), A1 [32K,64K), A2 [64K,96K), B [96K,112K)

static __device__ __forceinline__ uint32_t smem_u32(const void* p) {
    uint32_t a;
    asm("{ .reg .u64 t; cvta.to.shared.u64 t, %1; cvt.u32.u64 %0, t; }" : "=r"(a) : "l"(p));
    return a;
}
static __device__ __forceinline__ uint32_t cvt_tf32(float f) {
    uint32_t r;
    asm("cvt.rn.tf32.f32 %0, %1;" : "=r"(r) : "f"(f));
    return r;
}
static __device__ __forceinline__ void mma_tf32(float* d,
    uint32_t a0, uint32_t a1, uint32_t a2, uint32_t a3,
    uint32_t b0, uint32_t b1)
{
    asm volatile("mma.sync.aligned.m16n8k8.row.col.f32.tf32.tf32.f32 "
        "{%0,%1,%2,%3}, {%4,%5,%6,%7}, {%8,%9}, {%0,%1,%2,%3};"
        : "+f"(d[0]), "+f"(d[1]), "+f"(d[2]), "+f"(d[3])
        : "r"(a0), "r"(a1), "r"(a2), "r"(a3), "r"(b0), "r"(b1));
}

// Prefetch one 128-row feature tile (raw fp32) into a swizzled SMEM buffer.
// ALWAYS commits a group (cnt4==0 -> pure zero-fill, no GMEM reads) so the
// pipeline's pending-group count is identical on every iteration.
static __device__ __forceinline__ void prefetch_tile(
    const float4* gbase, uint32_t abase, int tid, int cnt4)
{
    #pragma unroll
    for (int i = 0; i < 8; i++) {
        int idx = tid + i * THREADS;
        int r = idx >> 4, c = idx & 15;
        uint32_t dst = abase + (((r << 4) | (c ^ (r & 7))) << 4);
        int cidx = (idx < cnt4) ? idx : 0;
        uint32_t sz = (idx < cnt4) ? 16u : 0u;       // OOB -> zero-fill
        asm volatile("cp.async.cg.shared.global [%0], [%1], 16, %2;"
                     :: "r"(dst), "l"(gbase + cidx), "r"(sz) : "memory");
    }
    asm volatile("cp.async.commit_group;" ::: "memory");
}

// Stage 1: quad transpose (xor 1).
static __device__ __forceinline__ void quad_transpose(
    const float (&v)[8][2], float4 (&c)[4], int odd)
{
    #pragma unroll
    for (int m = 0; m < 4; m++) {
        const int j0 = 2 * m, j1 = 2 * m + 1;
        float send0 = odd ? v[j0][0] : v[j1][0];
        float send1 = odd ? v[j0][1] : v[j1][1];
        float own0  = odd ? v[j1][0] : v[j0][0];
        float own1  = odd ? v[j1][1] : v[j0][1];
        float r0 = __shfl_xor_sync(~0u, send0, 1);
        float r1 = __shfl_xor_sync(~0u, send1, 1);
        c[m].x = odd ? r0 : own0;
        c[m].y = odd ? r1 : own1;
        c[m].z = odd ? own0 : r0;
        c[m].w = odd ? own1 : r1;
    }
}

// Stage 2: xor-4 exchange of chunks {1,3}; streaming full-line stores.
static __device__ __forceinline__ void pair_store(
    float4 (&c)[4], float* op, long offE, long offO,
    int colsub, int peven, bool okE, bool okO)
{
    float4 x1, x3;
    x1.x = __shfl_xor_sync(~0u, c[1].x, 4);
    x1.y = __shfl_xor_sync(~0u, c[1].y, 4);
    x1.z = __shfl_xor_sync(~0u, c[1].z, 4);
    x1.w = __shfl_xor_sync(~0u, c[1].w, 4);
    x3.x = __shfl_xor_sync(~0u, c[3].x, 4);
    x3.y = __shfl_xor_sync(~0u, c[3].y, 4);
    x3.z = __shfl_xor_sync(~0u, c[3].z, 4);
    x3.w = __shfl_xor_sync(~0u, c[3].w, 4);
    if (okE) __stcs((float4*)(op + offE + (peven ? 0 : 16) + colsub),      peven ? c[0] : x1);
    if (okO) __stcs((float4*)(op + offO + (peven ? 16 : 0) + colsub),      peven ? x1 : c[0]);
    if (okE) __stcs((float4*)(op + offE + 32 + (peven ? 0 : 16) + colsub), peven ? c[2] : x3);
    if (okO) __stcs((float4*)(op + offO + 32 + (peven ? 16 : 0) + colsub), peven ? x3 : c[2]);
}

// Persistent, 2 CTAs/SM, triple-buffered cp.async pipeline (2 tiles in flight).
__global__ __launch_bounds__(THREADS, 2) void assign_mma_kernel(
    const float4* __restrict__ feat4,
    const float4* __restrict__ proto4,
    float* __restrict__ out, int nrows, int ntiles)
{
    extern __shared__ char smem[];
    const uint32_t sbase = smem_u32(smem);
    uint4* B_s = (uint4*)(smem + 96 * 1024);

    const int tid = threadIdx.x;
    const int w = tid >> 5, lane = tid & 31;
    const int gid = lane >> 2, tig = lane & 3;
    const int odd = tig & 1, tigh = tig >> 1;
    const int colsub = 4 * (tigh + 2 * odd);
    const int peven = ((gid & 1) == 0);
    const int sw = gid << 2;
    const int rb = w * 16;

    // ---- stage prototypes once (tf32, swizzled) ----
    #pragma unroll
    for (int i = 0; i < 4; i++) {
        int idx = tid + i * THREADS;
        float4 v = proto4[idx];
        uint4 t;
        t.x = cvt_tf32(v.x); t.y = cvt_tf32(v.y);
        t.z = cvt_tf32(v.z); t.w = cvt_tf32(v.w);
        int n = idx >> 4, c = idx & 15;
        B_s[(n << 4) | (c ^ (n & 7))] = t;
    }
    const uint32_t* Bs32 = (const uint32_t*)B_s;

    const long t0 = blockIdx.x;
    const long stride = gridDim.x;

    // ---- prologue: prefetch tiles t0 (slot 0) and t0+stride (slot 1) ----
    {
        int cnt = min(RPB, nrows - (int)(t0 * RPB)) * 16;     // t0 < ntiles always
        prefetch_tile(feat4 + t0 * RPB * 16, sbase, tid, cnt);
        long t1 = t0 + stride;
        long tc1 = t1 < ntiles ? t1 : (long)(ntiles - 1);
        int cnt1 = (t1 < ntiles) ? min(RPB, nrows - (int)(tc1 * RPB)) * 16 : 0;
        prefetch_tile(feat4 + tc1 * RPB * 16, sbase + (1u << 15), tid, cnt1);
    }

    int cs = 0;   // compute slot (rotates 0,1,2)
    int ps = 2;   // prefetch slot = (cs+2)%3, maintained incrementally
    for (long tile = t0; tile < ntiles; tile += stride) {
        const long base = tile * RPB;
        const int rows = min(RPB, nrows - (int)base);

        // prefetch tile+2*stride into slot ps — always commit a group
        {
            long tn = tile + 2 * stride;
            long tc = tn < ntiles ? tn : (long)(ntiles - 1);
            int cnt = (tn < ntiles) ? min(RPB, nrows - (int)(tc * RPB)) * 16 : 0;
            prefetch_tile(feat4 + tc * RPB * 16, sbase + ((uint32_t)ps << 15), tid, cnt);
        }
        // two younger groups pending -> current tile's group drained
        asm volatile("cp.async.wait_group 2;" ::: "memory");
        __syncthreads();

        const float* Asf = (const float*)(smem + ((uint32_t)cs << 15));

        // ---- GEMM + fused row norms (raw fp32 -> cvt at use) ----
        float acc[8][4];
        float nrm[2] = {0.f, 0.f};
        #pragma unroll
        for (int j = 0; j < 8; j++)
            #pragma unroll
            for (int e = 0; e < 4; e++) acc[j][e] = 0.f;

        #pragma unroll
        for (int ks = 0; ks < 8; ks++) {
            int o0 = (ks * 8 + tig) ^ sw;
            int o1 = (ks * 8 + tig + 4) ^ sw;
            int r = rb + gid;
            float f0 = Asf[r * 64 + o0];
            float f1 = Asf[(r + 8) * 64 + o0];
            float f2 = Asf[r * 64 + o1];
            float f3 = Asf[(r + 8) * 64 + o1];
            nrm[0] += f0 * f0 + f2 * f2;   // row r
            nrm[1] += f1 * f1 + f3 * f3;   // row r+8
            uint32_t a0 = cvt_tf32(f0), a1 = cvt_tf32(f1);
            uint32_t a2 = cvt_tf32(f2), a3 = cvt_tf32(f3);
            #pragma unroll
            for (int j = 0; j < 8; j++) {
                int n = j * 8 + gid;
                mma_tf32(acc[j], a0, a1, a2, a3,
                         Bs32[n * 64 + o0], Bs32[n * 64 + o1]);
            }
        }

        // ---- scales: quad-reduce; sc = 5 / max(||f||, eps)  (tau=0.2) ----
        float sc[2];
        #pragma unroll
        for (int hf = 0; hf < 2; hf++) {
            float s = nrm[hf];
            s += __shfl_xor_sync(~0u, s, 1);
            s += __shfl_xor_sync(~0u, s, 2);
            sc[hf] = 5.0f / fmaxf(sqrtf(s), 1e-8f);
        }

        // ---- epilogue ----
        #pragma unroll
        for (int hf = 0; hf < 2; hf++) {
            int rE = rb + hf * 8 + (gid & ~1);
            int rO = rE + 1;
            float scv = sc[hf];
            bool okE = (rE < rows), okO = (rO < rows);
            long offE = (base + rE) * 64;
            long offO = (base + rO) * 64;

            float lg[8][2], ex[8][2];
            float s = 0.f;
            #pragma unroll
            for (int j = 0; j < 8; j++) {
                lg[j][0] = acc[j][2 * hf]     * scv;
                lg[j][1] = acc[j][2 * hf + 1] * scv;
                ex[j][0] = __expf(lg[j][0]);       // |logit| <= 5
                ex[j][1] = __expf(lg[j][1]);
                s += ex[j][0] + ex[j][1];
            }
            s += __shfl_xor_sync(~0u, s, 1);
            s += __shfl_xor_sync(~0u, s, 2);
            float inv = 1.0f / s;
            #pragma unroll
            for (int j = 0; j < 8; j++) {
                ex[j][0] *= inv;
                ex[j][1] *= inv;
            }

            float4 c[4];
            quad_transpose(lg, c, odd);
            pair_store(c, out, offE, offO, colsub, peven, okE, okO);
            quad_transpose(ex, c, odd);
            pair_store(c, out + (long)nrows * 64, offE, offO, colsub, peven, okE, okO);
        }
        __syncthreads();   // all reads of slot cs done before it is refilled

        cs = (cs + 1 == 3) ? 0 : cs + 1;
        ps = (ps + 1 == 3) ? 0 : ps + 1;
    }
}

extern "C" void kernel_launch(void* const* d_in, const int* in_sizes, int n_in,
                              void* d_out, int out_size) {
    const float4* feat4  = (const float4*)d_in[0];
    const float4* proto4 = (const float4*)d_in[1];
    float* out = (float*)d_out;
    int nrows = in_sizes[0] / 64;
    int ntiles = (nrows + RPB - 1) / RPB;
    cudaFuncSetAttribute(assign_mma_kernel,
                         cudaFuncAttributeMaxDynamicSharedMemorySize, SMEM_BYTES);
    int grid = 296;                    // 2 persistent CTAs per SM (148 SMs)
    if (grid > ntiles) grid = ntiles;
    assign_mma_kernel<<<grid, THREADS, SMEM_BYTES>>>(feat4, proto4, out, nrows, ntiles);
}